// round 5
// baseline (speedup 1.0000x reference)
#include <cuda_runtime.h>

#define NN 100000
#define EE 1600000
#define NPB 128                          // nodes per bucket (power of 2)
#define NBUCK_MAX ((NN + NPB - 1) / NPB) // 782
#define CHUNK 3584                       // edges per partition block

// ---- device scratch (no allocations allowed) ----
__device__ int2  g_part[EE];            // edges partitioned by dst bucket
__device__ int   g_bcnt[NBUCK_MAX];     // bucket totals
__device__ int   g_bbase[NBUCK_MAX + 1];
__device__ int   g_bcur[NBUCK_MAX];     // write cursors (re-init every replay)
__device__ float g_dinv[NN];
__device__ float g_px[NN];              // dinv[v]*x[v]
__device__ float g_s[NN];               // finalized layer-1 pre-activation
__device__ float2 g_pq[NN];             // dinv[v]*(max(s,0), min(s,0))
__device__ float g_c[64];               // c1=relu(W1)@W2, c2=min(W1,0)@W2
__device__ int   g_b1zero;
__device__ int   g_is64;

// ---- setup: dtype probe, b1-zero flag, fused coefs, zero bucket counters ----
__global__ void k_setup(const void* __restrict__ ei, const float* __restrict__ W1,
                        const float* __restrict__ b1, const float* __restrict__ W2,
                        int E, int N, int NB) {
    int tid = threadIdx.x;  // 1024 threads, 1 block
    __shared__ int bad;
    if (tid == 0) bad = 0;
    __syncthreads();
    if (tid < 256 && tid < E) {
        long long v = ((const long long*)ei)[tid];  // in-bounds under both layouts
        if (v < 0 || v >= (long long)N) atomicExch(&bad, 1);
    }
    __syncthreads();
    if (tid == 0) {
        g_is64 = !bad;
        int z = 1;
        for (int k = 0; k < 16; k++)
            if (b1[k] != 0.f) z = 0;
        g_b1zero = z;
    }
    if (tid < 32) {
        float c1 = 0.f, c2 = 0.f;
#pragma unroll
        for (int k = 0; k < 16; k++) {
            float w  = W1[k];
            float wv = W2[k * 32 + tid];
            c1 += fmaxf(w, 0.f) * wv;
            c2 += fminf(w, 0.f) * wv;
        }
        g_c[tid] = c1;
        g_c[32 + tid] = c2;
    }
    for (int b = tid; b < NB; b += 1024) g_bcnt[b] = 0;
}

// ---- histogram of dst buckets (smem-privatized) ----
__global__ void k_hist(const void* __restrict__ eiv, int E, int NB) {
    __shared__ int sh[NBUCK_MAX];
    int tid = threadIdx.x;
    for (int i = tid; i < NB; i += blockDim.x) sh[i] = 0;
    __syncthreads();
    int gid = blockIdx.x * blockDim.x + tid;
    int stride = gridDim.x * blockDim.x;
    if (g_is64) {
        const long long* dst = (const long long*)eiv + E;
        for (int e = gid; e < E; e += stride) atomicAdd(&sh[((int)dst[e]) >> 7], 1);
    } else {
        const int* dst = (const int*)eiv + E;
        for (int e = gid; e < E; e += stride) atomicAdd(&sh[dst[e] >> 7], 1);
    }
    __syncthreads();
    for (int i = tid; i < NB; i += blockDim.x)
        if (sh[i]) atomicAdd(&g_bcnt[i], sh[i]);
}

// ---- exclusive scan of bucket counts (single block, 1024 threads) ----
__global__ void k_scan(int E, int NB) {
    __shared__ int s[1024];
    int tid = threadIdx.x;
    int my = (tid < NB) ? g_bcnt[tid] : 0;
    s[tid] = my;
    for (int off = 1; off < 1024; off <<= 1) {
        __syncthreads();
        int v = (tid >= off) ? s[tid - off] : 0;
        __syncthreads();
        if (tid >= off) s[tid] += v;
    }
    __syncthreads();
    if (tid < NB) {
        int excl = s[tid] - my;
        g_bbase[tid] = excl;
        g_bcur[tid]  = excl;
    }
    if (tid == 0) g_bbase[NB] = E;
}

// ---- partition edges by dst bucket (smem-staged, block-aggregated cursors) ----
__global__ void k_part(const void* __restrict__ eiv, int E, int NB) {
    __shared__ int2 se[CHUNK];                 // 28 KB
    __shared__ unsigned short srank[CHUNK];    // 7 KB
    __shared__ int scnt[NBUCK_MAX];            // 3.1 KB
    __shared__ int sbase[NBUCK_MAX];           // 3.1 KB
    int tid = threadIdx.x;  // 256
    for (int i = tid; i < NB; i += 256) scnt[i] = 0;
    __syncthreads();
    int e0 = blockIdx.x * CHUNK;
    int cnt = min(CHUNK, E - e0);
    if (g_is64) {
        const long long* sp = (const long long*)eiv;
        const long long* dp = sp + E;
        for (int i = tid; i < cnt; i += 256) {
            int ss = (int)sp[e0 + i], dd = (int)dp[e0 + i];
            se[i] = make_int2(ss, dd);
            srank[i] = (unsigned short)atomicAdd(&scnt[dd >> 7], 1);
        }
    } else {
        const int* sp = (const int*)eiv;
        const int* dp = sp + E;
        for (int i = tid; i < cnt; i += 256) {
            int ss = sp[e0 + i], dd = dp[e0 + i];
            se[i] = make_int2(ss, dd);
            srank[i] = (unsigned short)atomicAdd(&scnt[dd >> 7], 1);
        }
    }
    __syncthreads();
    for (int i = tid; i < NB; i += 256)
        if (scnt[i]) sbase[i] = atomicAdd(&g_bcur[i], scnt[i]);
    __syncthreads();
    for (int i = tid; i < cnt; i += 256) {
        int2 e = se[i];
        g_part[sbase[e.y >> 7] + (int)srank[i]] = e;
    }
}

// ---- fused: degree count (smem) + dinv + px ----
__global__ void k_degpx(const float* __restrict__ x, int N) {
    __shared__ int sdeg[NPB];
    int tid = threadIdx.x;  // 256
    int b = blockIdx.x;
    if (tid < NPB) sdeg[tid] = 0;
    __syncthreads();
    int lo = g_bbase[b], hi = g_bbase[b + 1];
    for (int i = lo + tid; i < hi; i += 256)
        atomicAdd(&sdeg[g_part[i].y & (NPB - 1)], 1);
    __syncthreads();
    int v = b * NPB + tid;
    if (tid < NPB && v < N) {
        float dv = rsqrtf((float)sdeg[tid] + 1.0f);
        g_dinv[v] = dv;
        g_px[v]   = dv * x[v];
    }
}

// ---- fused: layer-1 smem scatter + finalize s + p/q split ----
__global__ void k_scat1(int N) {
    __shared__ float ss[NPB];
    int tid = threadIdx.x;  // 256
    int b = blockIdx.x;
    if (tid < NPB) ss[tid] = 0.f;
    __syncthreads();
    int lo = g_bbase[b], hi = g_bbase[b + 1];
    for (int i = lo + tid; i < hi; i += 256) {
        int2 e = g_part[i];
        atomicAdd(&ss[e.y & (NPB - 1)], __ldg(&g_px[e.x]));
    }
    __syncthreads();
    int v = b * NPB + tid;
    if (tid < NPB && v < N) {
        float dv = g_dinv[v];
        float s  = dv * (ss[tid] + g_px[v]);  // + self-loop term
        g_s[v] = s;
        float p = fmaxf(s, 0.f), q = fminf(s, 0.f);
        g_pq[v] = make_float2(dv * p, dv * q);
    }
}

// ---- fused: layer-2 smem scatter + output projection ----
__global__ void k_scat2out(const float* __restrict__ W1, const float* __restrict__ b1,
                           const float* __restrict__ W2, const float* __restrict__ b2,
                           float* __restrict__ out, int N) {
    __shared__ float sP[NPB], sQ[NPB];
    __shared__ float sagg[NPB * 16];    // fallback (b1 != 0) accumulator
    __shared__ float sc[64], sb2[32], sW2[512], sW1[16], sb1[16];
    int bz = g_b1zero;
    int tid = threadIdx.x;  // 256
    int b = blockIdx.x;
    if (tid < 64) sc[tid] = g_c[tid];
    if (tid < 32) sb2[tid] = b2[tid];
    if (bz) {
        if (tid < NPB) { sP[tid] = 0.f; sQ[tid] = 0.f; }
    } else {
        for (int k = tid; k < NPB * 16; k += 256) sagg[k] = 0.f;
        for (int k = tid; k < 512; k += 256) sW2[k] = W2[k];
        if (tid < 16) { sW1[tid] = W1[tid]; sb1[tid] = b1[tid]; }
    }
    __syncthreads();
    int lo = g_bbase[b], hi = g_bbase[b + 1];
    if (bz) {
        for (int i = lo + tid; i < hi; i += 256) {
            int2 e = g_part[i];
            float2 t = __ldg(&g_pq[e.x]);
            int l = e.y & (NPB - 1);
            atomicAdd(&sP[l], t.x);
            atomicAdd(&sQ[l], t.y);
        }
    } else {
        for (int i = lo + tid; i < hi; i += 256) {
            int2 e = g_part[i];
            float sv = __ldg(&g_s[e.x]);
            float ns = __ldg(&g_dinv[e.x]);
            int l = e.y & (NPB - 1);
#pragma unroll
            for (int k = 0; k < 16; k++) {
                float h = fmaxf(sv * sW1[k] + sb1[k], 0.f);
                atomicAdd(&sagg[l * 16 + k], ns * h);
            }
        }
    }
    __syncthreads();
    int v = b * NPB + tid;
    if (tid < NPB && v < N) {
        float dv = g_dinv[v];
        float o[32];
        if (bz) {
            float2 pq = g_pq[v];  // self-loop term (already ×dinv[v] once)
            float P = dv * (sP[tid] + pq.x);
            float Q = dv * (sQ[tid] + pq.y);
#pragma unroll
            for (int j = 0; j < 32; j++) o[j] = P * sc[j] + Q * sc[32 + j] + sb2[j];
        } else {
            float sv = g_s[v];
            float n2 = dv * dv;
            float tot[16];
#pragma unroll
            for (int k = 0; k < 16; k++) {
                float h = fmaxf(sv * sW1[k] + sb1[k], 0.f);
                tot[k] = dv * sagg[tid * 16 + k] + n2 * h;
            }
#pragma unroll
            for (int j = 0; j < 32; j++) {
                float acc = sb2[j];
#pragma unroll
                for (int k = 0; k < 16; k++) acc += tot[k] * sW2[k * 32 + j];
                o[j] = acc;
            }
        }
        float4* po = reinterpret_cast<float4*>(out + (size_t)v * 32);
#pragma unroll
        for (int j = 0; j < 8; j++)
            po[j] = make_float4(o[4 * j], o[4 * j + 1], o[4 * j + 2], o[4 * j + 3]);
    }
}

extern "C" void kernel_launch(void* const* d_in, const int* in_sizes, int n_in,
                              void* d_out, int out_size) {
    const float* x  = (const float*)d_in[0];
    const void*  ei = d_in[1];
    const float* W1 = (const float*)d_in[2];
    const float* b1 = (const float*)d_in[3];
    const float* W2 = (const float*)d_in[4];
    const float* b2 = (const float*)d_in[5];
    float* out = (float*)d_out;

    int N = in_sizes[0];
    int E = in_sizes[1] / 2;
    int NB = (N + NPB - 1) / NPB;

    int gPart = (E + CHUNK - 1) / CHUNK;

    k_setup<<<1, 1024>>>(ei, W1, b1, W2, E, N, NB);
    k_hist<<<296, 256>>>(ei, E, NB);
    k_scan<<<1, 1024>>>(E, NB);
    k_part<<<gPart, 256>>>(ei, E, NB);
    k_degpx<<<NB, 256>>>(x, N);
    k_scat1<<<NB, 256>>>(N);
    k_scat2out<<<NB, 256>>>(W1, b1, W2, b2, out, N);
}

// round 6
// speedup vs baseline: 1.2549x; 1.2549x over previous
#include <cuda_runtime.h>

#define NN 100000
#define EE 1600000
#define BLK 256

// ---- device scratch (no allocations allowed) ----
__device__ int    g_src32[EE];     // int64->int32 converted edges (only if needed)
__device__ int    g_dst32[EE];
__device__ float  g_deg[NN];
__device__ float  g_dinv[NN];
__device__ float  g_px[NN];        // dinv[v]*x[v]
__device__ float  g_s[NN];         // raw layer-1 aggregate, then finalized s
__device__ float2 g_pq[NN];        // dinv[v]*(max(s,0), min(s,0))
__device__ float2 g_PQ[NN];        // raw layer-2 (P,Q) aggregate (incl. self term)
__device__ float  g_agg[NN * 16];  // general-path fallback aggregate
__device__ float  g_c[64];         // c1=relu(W1)@W2, c2=min(W1,0)@W2
__device__ int    g_b1zero;
__device__ int    g_is64;

__device__ __forceinline__ int4 ldcs4(const int* p) {
    return __ldcs(reinterpret_cast<const int4*>(p));
}

__device__ __forceinline__ void red2(float2* addr, float2 v) {
    asm volatile("red.add.v2.f32 [%0], {%1, %2};"
                 :: "l"(addr), "f"(v.x), "f"(v.y) : "memory");
}

// ---- setup: dtype probe + fused coefficients + zero degree array ----
__global__ void k_setup(const void* __restrict__ ei, const float* __restrict__ W1,
                        const float* __restrict__ b1, const float* __restrict__ W2,
                        int E, int N) {
    int tid = threadIdx.x;
    if (blockIdx.x == 0) {
        __shared__ int bad;
        if (tid == 0) bad = 0;
        __syncthreads();
        if (tid < E) {
            long long v = ((const long long*)ei)[tid];  // first 256 slots: in-bounds both layouts
            if (v < 0 || v >= (long long)N) atomicExch(&bad, 1);
        }
        __syncthreads();
        if (tid == 0) {
            g_is64 = !bad;
            int z = 1;
            for (int k = 0; k < 16; k++)
                if (b1[k] != 0.f) z = 0;
            g_b1zero = z;
        }
        if (tid < 32) {
            float c1 = 0.f, c2 = 0.f;
#pragma unroll
            for (int k = 0; k < 16; k++) {
                float w  = W1[k];
                float wv = W2[k * 32 + tid];
                c1 += fmaxf(w, 0.f) * wv;
                c2 += fminf(w, 0.f) * wv;
            }
            g_c[tid] = c1;
            g_c[32 + tid] = c2;
        }
    }
    int v = blockIdx.x * BLK + tid;
    if (v < N) {
        g_deg[v] = 0.f;
        bool bz = true;
#pragma unroll
        for (int k = 0; k < 16; k++)
            if (b1[k] != 0.f) bz = false;
        if (!bz) {
            float4 z = make_float4(0.f, 0.f, 0.f, 0.f);
            float4* a = reinterpret_cast<float4*>(&g_agg[v * 16]);
            a[0] = z; a[1] = z; a[2] = z; a[3] = z;
        }
    }
}

// ---- pass 1: degree atomics (+ one-time int64->int32 conversion), 4 edges/thread ----
__global__ void k_deg(const void* __restrict__ eiv, int E) {
    int e0 = 4 * (blockIdx.x * blockDim.x + threadIdx.x);
    if (e0 >= E) return;
    if (g_is64) {
        const long long* ei = (const long long*)eiv;
        if (e0 + 3 < E) {
            longlong2 s01 = __ldcs(reinterpret_cast<const longlong2*>(ei + e0));
            longlong2 s23 = __ldcs(reinterpret_cast<const longlong2*>(ei + e0 + 2));
            longlong2 d01 = __ldcs(reinterpret_cast<const longlong2*>(ei + E + e0));
            longlong2 d23 = __ldcs(reinterpret_cast<const longlong2*>(ei + E + e0 + 2));
            int4 sv = make_int4((int)s01.x, (int)s01.y, (int)s23.x, (int)s23.y);
            int4 dv = make_int4((int)d01.x, (int)d01.y, (int)d23.x, (int)d23.y);
            *reinterpret_cast<int4*>(&g_src32[e0]) = sv;
            *reinterpret_cast<int4*>(&g_dst32[e0]) = dv;
            atomicAdd(&g_deg[dv.x], 1.f);
            atomicAdd(&g_deg[dv.y], 1.f);
            atomicAdd(&g_deg[dv.z], 1.f);
            atomicAdd(&g_deg[dv.w], 1.f);
        } else {
            for (int e = e0; e < E; e++) {
                int s = (int)ei[e], d = (int)ei[E + e];
                g_src32[e] = s; g_dst32[e] = d;
                atomicAdd(&g_deg[d], 1.f);
            }
        }
    } else {
        const int* dst = (const int*)eiv + E;
        if (e0 + 3 < E) {
            int4 dv = ldcs4(dst + e0);
            atomicAdd(&g_deg[dv.x], 1.f);
            atomicAdd(&g_deg[dv.y], 1.f);
            atomicAdd(&g_deg[dv.z], 1.f);
            atomicAdd(&g_deg[dv.w], 1.f);
        } else {
            for (int e = e0; e < E; e++) atomicAdd(&g_deg[dst[e]], 1.f);
        }
    }
}

// ---- pass 2: dinv = rsqrt(deg+1); px; raw s init = self term ----
__global__ void k_node1(const float* __restrict__ x, int n) {
    int v = blockIdx.x * blockDim.x + threadIdx.x;
    if (v >= n) return;
    float dv  = rsqrtf(g_deg[v] + 1.0f);
    g_dinv[v] = dv;
    float pxv = dv * x[v];
    g_px[v]   = pxv;
    g_s[v]    = pxv;
}

// ---- pass 3: layer-1 raw scatter: s_raw[dst] += px[src], 4 edges/thread ----
__global__ void k_scat1(const void* __restrict__ eiv, int E) {
    const int* srcp = g_is64 ? g_src32 : (const int*)eiv;
    const int* dstp = g_is64 ? g_dst32 : (const int*)eiv + E;
    int e0 = 4 * (blockIdx.x * blockDim.x + threadIdx.x);
    if (e0 >= E) return;
    if (e0 + 3 < E) {
        int4 s = ldcs4(srcp + e0);
        int4 d = ldcs4(dstp + e0);
        float a0 = __ldg(&g_px[s.x]), a1 = __ldg(&g_px[s.y]);
        float a2 = __ldg(&g_px[s.z]), a3 = __ldg(&g_px[s.w]);
        atomicAdd(&g_s[d.x], a0); atomicAdd(&g_s[d.y], a1);
        atomicAdd(&g_s[d.z], a2); atomicAdd(&g_s[d.w], a3);
    } else {
        for (int e = e0; e < E; e++)
            atomicAdd(&g_s[dstp[e]], __ldg(&g_px[srcp[e]]));
    }
}

// ---- pass 4: finalize s; pq split; raw PQ init = self term ----
__global__ void k_node2(int n) {
    int v = blockIdx.x * blockDim.x + threadIdx.x;
    if (v >= n) return;
    float dv = g_dinv[v];
    float s  = dv * g_s[v];
    g_s[v]   = s;
    float p = fmaxf(s, 0.f), q = fminf(s, 0.f);
    float2 pq = make_float2(dv * p, dv * q);
    g_pq[v] = pq;
    g_PQ[v] = pq;
}

// ---- pass 5: layer-2 raw scatter, 4 edges/thread, 1 v2-RED/edge ----
__global__ void k_scat2(const void* __restrict__ eiv,
                        const float* __restrict__ W1,
                        const float* __restrict__ b1, int E) {
    const int* srcp = g_is64 ? g_src32 : (const int*)eiv;
    const int* dstp = g_is64 ? g_dst32 : (const int*)eiv + E;
    int bz = g_b1zero;
    int e0 = 4 * (blockIdx.x * blockDim.x + threadIdx.x);
    if (e0 >= E) return;
    if (bz) {
        if (e0 + 3 < E) {
            int4 s = ldcs4(srcp + e0);
            int4 d = ldcs4(dstp + e0);
            float2 t0 = __ldg(&g_pq[s.x]), t1 = __ldg(&g_pq[s.y]);
            float2 t2 = __ldg(&g_pq[s.z]), t3 = __ldg(&g_pq[s.w]);
            red2(&g_PQ[d.x], t0); red2(&g_PQ[d.y], t1);
            red2(&g_PQ[d.z], t2); red2(&g_PQ[d.w], t3);
        } else {
            for (int e = e0; e < E; e++) red2(&g_PQ[dstp[e]], __ldg(&g_pq[srcp[e]]));
        }
    } else {
        __shared__ float sW1[16], sb1[16];
        if (threadIdx.x < 16) { sW1[threadIdx.x] = W1[threadIdx.x]; sb1[threadIdx.x] = b1[threadIdx.x]; }
        __syncthreads();
        int eEnd = min(e0 + 4, E);
        for (int e = e0; e < eEnd; e++) {
            int s = srcp[e], d = dstp[e];
            float sv = __ldg(&g_s[s]);
            float ns = __ldg(&g_dinv[s]);
#pragma unroll
            for (int k = 0; k < 16; k++) {
                float h = fmaxf(sv * sW1[k] + sb1[k], 0.f);
                atomicAdd(&g_agg[d * 16 + k], ns * h);
            }
        }
    }
}

// ---- pass 6: output projection (streaming stores) ----
__global__ void k_out(const float* __restrict__ W1, const float* __restrict__ b1,
                      const float* __restrict__ W2, const float* __restrict__ b2,
                      float* __restrict__ out, int n) {
    __shared__ float sc[64];
    __shared__ float sb2[32];
    __shared__ float sW2[512];
    __shared__ float sW1[16], sb1[16];
    int bz = g_b1zero;
    int t = threadIdx.x;
    if (t < 64) sc[t] = g_c[t];
    if (t < 32) sb2[t] = b2[t];
    if (!bz) {
        for (int k = t; k < 512; k += blockDim.x) sW2[k] = W2[k];
        if (t < 16) { sW1[t] = W1[t]; sb1[t] = b1[t]; }
    }
    __syncthreads();
    int v = blockIdx.x * blockDim.x + t;
    if (v >= n) return;

    float o[32];
    float dv = g_dinv[v];
    if (bz) {
        float2 PQ = g_PQ[v];
        float P = dv * PQ.x, Q = dv * PQ.y;
#pragma unroll
        for (int j = 0; j < 32; j++) o[j] = P * sc[j] + Q * sc[32 + j] + sb2[j];
    } else {
        float sv = g_s[v];
        float n2 = dv * dv;
        float tot[16];
#pragma unroll
        for (int k = 0; k < 16; k++) {
            float h = fmaxf(sv * sW1[k] + sb1[k], 0.f);
            tot[k] = dv * g_agg[v * 16 + k] + n2 * h;
        }
#pragma unroll
        for (int j = 0; j < 32; j++) {
            float acc = sb2[j];
#pragma unroll
            for (int k = 0; k < 16; k++) acc += tot[k] * sW2[k * 32 + j];
            o[j] = acc;
        }
    }
    float4* po = reinterpret_cast<float4*>(out + (size_t)v * 32);
#pragma unroll
    for (int j = 0; j < 8; j++)
        __stcs(po + j, make_float4(o[4 * j], o[4 * j + 1], o[4 * j + 2], o[4 * j + 3]));
}

extern "C" void kernel_launch(void* const* d_in, const int* in_sizes, int n_in,
                              void* d_out, int out_size) {
    const float* x  = (const float*)d_in[0];
    const void*  ei = d_in[1];
    const float* W1 = (const float*)d_in[2];
    const float* b1 = (const float*)d_in[3];
    const float* W2 = (const float*)d_in[4];
    const float* b2 = (const float*)d_in[5];
    float* out = (float*)d_out;

    int N = in_sizes[0];
    int E = in_sizes[1] / 2;

    int gN  = (N + BLK - 1) / BLK;
    int gE4 = ((E + 3) / 4 + BLK - 1) / BLK;

    k_setup<<<gN, BLK>>>(ei, W1, b1, W2, E, N);
    k_deg<<<gE4, BLK>>>(ei, E);
    k_node1<<<gN, BLK>>>(x, N);
    k_scat1<<<gE4, BLK>>>(ei, E);
    k_node2<<<gN, BLK>>>(N);
    k_scat2<<<gE4, BLK>>>(ei, W1, b1, E);
    k_out<<<gN, BLK>>>(W1, b1, W2, b2, out, N);
}